// round 4
// baseline (speedup 1.0000x reference)
#include <cuda_runtime.h>
#include <cstdint>

// Problem constants
#define NB 4
#define NH 16
#define SL 2048
#define HD 64
#define TOPKK 128

// Tiling
#define TQ 16
#define CK 256
#define NTHR 512
#define WCAP 640   // per-warp bucket buffer capacity

// SMEM layout (bytes)
#define SM_KEYS  0
#define SM_QS    (TQ*SL*4)                 // 131072
#define SM_KS    (SM_QS + TQ*HD*4)         // 135168   K pair-staging (128 rows x 64 floats = 32KB)
#define SM_SELI  (SM_KS + (CK/2)*64*4)     // 167936
#define SM_SELW  (SM_SELI + TQ*TOPKK*4)    // 176128
#define SM_WBUF  (SM_SELW + TQ*TOPKK*4)    // 184320
#define SM_TOTAL (SM_WBUF + 16*WCAP*4)     // 225280

typedef unsigned long long u64;

__device__ __forceinline__ void fma2(u64& d, u64 a, u64 b) {
    asm("fma.rn.f32x2 %0, %1, %2, %0;" : "+l"(d) : "l"(a), "l"(b));
}
__device__ __forceinline__ u64 bcast2(float x) {
    u64 r; uint32_t u = __float_as_uint(x);
    asm("mov.b64 %0, {%1, %1};" : "=l"(r) : "r"(u));
    return r;
}
__device__ __forceinline__ float2 unpk2(u64 v) {
    uint32_t lo, hi;
    asm("mov.b64 {%0, %1}, %2;" : "=r"(lo), "=r"(hi) : "l"(v));
    return make_float2(__uint_as_float(lo), __uint_as_float(hi));
}

// order-preserving float -> uint key (monotone increasing), branchless
__device__ __forceinline__ uint32_t f2k(float f) {
    uint32_t b = __float_as_uint(f);
    return b ^ (0x80000000u | (uint32_t)((int32_t)b >> 31));
}
__device__ __forceinline__ float k2f(uint32_t k) {
    uint32_t b = k ^ ((k >> 31) ? 0x80000000u : 0xFFFFFFFFu);
    return __uint_as_float(b);
}

__global__ void __launch_bounds__(NTHR, 1)
topk_attn_kernel(const float* __restrict__ Qg, const float* __restrict__ Kg,
                 const float* __restrict__ Vg, float* __restrict__ Og)
{
    extern __shared__ char smem[];
    uint32_t* keys = (uint32_t*)(smem + SM_KEYS);   // [TQ][SL]
    float4*   Qs4  = (float4*)(smem + SM_QS);       // [TQ][16] linear
    float4*   Ks4  = (float4*)(smem + SM_KS);       // [128 pair-rows][16] swizzled
    int*      seli = (int*)(smem + SM_SELI);
    float*    selw = (float*)(smem + SM_SELW);
    uint32_t* wbase = (uint32_t*)(smem + SM_WBUF);

    const int qt  = (gridDim.x - 1) - blockIdx.x;   // heavy tiles scheduled first
    const int bh  = blockIdx.y;
    const int tid = threadIdx.x;
    const int qbase  = qt * TQ;
    const int kneed  = qbase + TQ;
    const int nchunk = (kneed + CK - 1) / CK;

    const float* Qb = Qg + ((size_t)bh * SL + qbase) * HD;
    const float* Kb = Kg + (size_t)bh * SL * HD;
    const float* Vb = Vg + (size_t)bh * SL * HD;

    // ---- stage Q tile (linear, broadcast-read later) ----
    if (tid < 256) {
        int qi = tid >> 4, c = tid & 15;
        Qs4[qi * 16 + c] = ((const float4*)(Qb + qi * HD))[c];
    }
    __syncthreads();

    // ---- Phase 1: QK^T with f32x2 packed FMA, d split into two 32-halves ----
    const int qp = tid >> 6;          // 0..7  -> queries 2qp, 2qp+1
    const int kg = tid & 63;          // 0..63 -> keys 4kg..4kg+3 (pair rows 2kg, 2kg+1)
    const int q0 = 2 * qp, q1 = q0 + 1;
    const int qg0 = qbase + q0, qg1 = qg0 + 1;
    const int p0r = 2 * kg, p1r = 2 * kg + 1;
    const int sw0 = p0r & 15, sw1 = p1r & 15;

    for (int dh = 0; dh < 2; dh++) {
        // Q half into registers (broadcast LDS within warp)
        float qr0[32], qr1[32];
        #pragma unroll
        for (int c = 0; c < 8; c++) {
            *(float4*)&qr0[4 * c] = Qs4[q0 * 16 + dh * 8 + c];
            *(float4*)&qr1[4 * c] = Qs4[q1 * 16 + dh * 8 + c];
        }
        for (int ch = 0; ch < nchunk; ch++) {
            const int kbase = ch * CK;
            // stage K half as interleaved key-pairs:
            // Ks4[p][c^ (p&15)] = (K[2p][2c],K[2p+1][2c],K[2p][2c+1],K[2p+1][2c+1])
            const float* Ksrc = Kb + (size_t)kbase * HD + dh * 32;
            #pragma unroll
            for (int t = 0; t < 2; t++) {
                int idx = t * NTHR + tid;           // 0..1023
                int p = idx >> 3, c2 = idx & 7;
                float4 f0 = *(const float4*)(Ksrc + (size_t)(2 * p) * HD + c2 * 4);
                float4 f1 = *(const float4*)(Ksrc + (size_t)(2 * p + 1) * HD + c2 * 4);
                int sw = p & 15;
                Ks4[p * 16 + ((2 * c2)     ^ sw)] = make_float4(f0.x, f1.x, f0.y, f1.y);
                Ks4[p * 16 + ((2 * c2 + 1) ^ sw)] = make_float4(f0.z, f1.z, f0.w, f1.w);
            }
            __syncthreads();

            u64 a00 = 0, a01 = 0, a10 = 0, a11 = 0;
            #pragma unroll
            for (int d4 = 0; d4 < 8; d4++) {
                const int c0 = 2 * d4;
                ulonglong2 A0 = *(const ulonglong2*)&Ks4[p0r * 16 + ( c0      ^ sw0)];
                ulonglong2 A1 = *(const ulonglong2*)&Ks4[p0r * 16 + ((c0 + 1) ^ sw0)];
                ulonglong2 B0 = *(const ulonglong2*)&Ks4[p1r * 16 + ( c0      ^ sw1)];
                ulonglong2 B1 = *(const ulonglong2*)&Ks4[p1r * 16 + ((c0 + 1) ^ sw1)];
                #pragma unroll
                for (int j = 0; j < 4; j++) {
                    u64 k0 = (j == 0) ? A0.x : (j == 1) ? A0.y : (j == 2) ? A1.x : A1.y;
                    u64 k1 = (j == 0) ? B0.x : (j == 1) ? B0.y : (j == 2) ? B1.x : B1.y;
                    u64 P0 = bcast2(qr0[4 * d4 + j]);
                    u64 P1 = bcast2(qr1[4 * d4 + j]);
                    fma2(a00, k0, P0); fma2(a01, k1, P0);
                    fma2(a10, k0, P1); fma2(a11, k1, P1);
                }
            }

            float* kr0 = (float*)(keys + q0 * SL + kbase + 4 * kg);
            float* kr1 = (float*)(keys + q1 * SL + kbase + 4 * kg);
            float2 u0 = unpk2(a00), u1 = unpk2(a01);
            float2 v0 = unpk2(a10), v1 = unpk2(a11);
            if (dh == 0) {
                *(float4*)kr0 = make_float4(u0.x, u0.y, u1.x, u1.y);
                *(float4*)kr1 = make_float4(v0.x, v0.y, v1.x, v1.y);
            } else {
                float4 pA = *(float4*)kr0;
                float4 pB = *(float4*)kr1;
                float sA[4] = { pA.x + u0.x, pA.y + u0.y, pA.z + u1.x, pA.w + u1.y };
                float sB[4] = { pB.x + v0.x, pB.y + v0.y, pB.z + v1.x, pB.w + v1.y };
                const int k0i = kbase + 4 * kg;
                uint4 oA, oB;
                oA.x = f2k((k0i     <= qg0) ? sA[0] : -3.402823466e38f);
                oA.y = f2k((k0i + 1 <= qg0) ? sA[1] : -3.402823466e38f);
                oA.z = f2k((k0i + 2 <= qg0) ? sA[2] : -3.402823466e38f);
                oA.w = f2k((k0i + 3 <= qg0) ? sA[3] : -3.402823466e38f);
                oB.x = f2k((k0i     <= qg1) ? sB[0] : -3.402823466e38f);
                oB.y = f2k((k0i + 1 <= qg1) ? sB[1] : -3.402823466e38f);
                oB.z = f2k((k0i + 2 <= qg1) ? sB[2] : -3.402823466e38f);
                oB.w = f2k((k0i + 3 <= qg1) ? sB[3] : -3.402823466e38f);
                *(uint4*)kr0 = oA;
                *(uint4*)kr1 = oB;
            }
            __syncthreads();
        }
    }

    // ---- Phase 2: exact top-128 per query (one warp per query) ----
    const int warp = tid >> 5, lane = tid & 31;
    const unsigned FULL = 0xFFFFFFFFu;
    const uint32_t lmask = (1u << lane) - 1u;
    const float scale = 0.125f;

    const int qi = warp;                 // 0..15
    const int qg = qbase + qi;
    const int n  = qg + 1;
    uint32_t* krow = keys + qi * SL;

    uint32_t T = 0; int need_eq = 0;
    if (n > TOPKK) {
        uint32_t prefix = 0; int r = TOPKK;
        const uint4* krow4 = (const uint4*)krow;
        const int nv4 = n >> 2;
        // 8-round binary descent on the top byte (uint4-vectorized scans)
        #pragma unroll
        for (int b = 31; b >= 24; b--) {
            const uint32_t test = prefix | (1u << b);
            const uint32_t hm = ~((1u << b) - 1u);
            int c = 0;
            for (int i = lane; i < nv4; i += 32) {
                uint4 v = krow4[i];
                c += ((v.x & hm) == test);
                c += ((v.y & hm) == test);
                c += ((v.z & hm) == test);
                c += ((v.w & hm) == test);
            }
            for (int i = (nv4 << 2) + lane; i < n; i += 32)
                c += ((krow[i] & hm) == test);
            c = __reduce_add_sync(FULL, c);
            if (c >= r) prefix = test; else r -= c;
        }
        // compact the threshold's top-byte bucket (overflow-guarded)
        uint32_t* wb = wbase + warp * WCAP;
        int m = 0;
        for (int base = 0; base < n; base += 32) {
            int i = base + lane;
            uint32_t k = (i < n) ? krow[i] : 0u;
            bool mt = (i < n) && ((k & 0xFF000000u) == prefix);
            uint32_t bal = __ballot_sync(FULL, mt);
            int pos = m + __popc(bal & lmask);
            if (mt && pos < WCAP) wb[pos] = k;
            m += __popc(bal);
        }
        if (m <= WCAP) {
            // shrinking descent over the low 24 bits: count, then compact survivors in place
            #pragma unroll 1
            for (int b = 23; b >= 0; b--) {
                const uint32_t bit = 1u << b;
                int c = 0;
                for (int i = lane; i < m; i += 32) c += ((wb[i] & bit) != 0);
                c = __reduce_add_sync(FULL, c);
                bool keepset;
                if (c >= r) keepset = true;
                else { r -= c; keepset = false; }
                int nm = 0;
                for (int base = 0; base < m; base += 32) {
                    int i = base + lane;
                    uint32_t k = (i < m) ? wb[i] : 0u;
                    bool keep = (i < m) && (((k & bit) != 0) == keepset);
                    uint32_t bal = __ballot_sync(FULL, keep);
                    if (keep) wb[nm + __popc(bal & lmask)] = k;
                    nm += __popc(bal);
                }
                m = nm;
                if (keepset) prefix |= bit;
            }
            T = prefix; need_eq = r;
        } else {
            // rare fallback: full-row descent on the remaining 24 bits
            #pragma unroll 1
            for (int b = 23; b >= 0; b--) {
                const uint32_t test = prefix | (1u << b);
                const uint32_t hm = ~((1u << b) - 1u);
                int c = 0;
                for (int i = lane; i < nv4; i += 32) {
                    uint4 v = krow4[i];
                    c += ((v.x & hm) == test);
                    c += ((v.y & hm) == test);
                    c += ((v.z & hm) == test);
                    c += ((v.w & hm) == test);
                }
                for (int i = (nv4 << 2) + lane; i < n; i += 32)
                    c += ((krow[i] & hm) == test);
                c = __reduce_add_sync(FULL, c);
                if (c >= r) prefix = test; else r -= c;
            }
            T = prefix; need_eq = r;
        }
    }

    // weight pass: select exactly topk (ties -> lowest index), exp relative to threshold
    const float ref = (n > TOPKK) ? k2f(T) : 0.0f;
    int* si = seli + qi * TOPKK;
    float* sw = selw + qi * TOPKK;
    int neq = 0, nsel = 0;
    float dsum = 0.f;
    for (int base = 0; base < n; base += 32) {
        int i = base + lane;
        uint32_t k = (i < n) ? krow[i] : 0u;
        bool gt = (i < n) && (k > T);
        bool eq = (i < n) && (k == T);
        uint32_t ebal = __ballot_sync(FULL, eq);
        bool sel = gt || (eq && (neq + __popc(ebal & lmask)) < need_eq);
        uint32_t sbal = __ballot_sync(FULL, sel);
        if (sel) {
            float w = __expf((k2f(k) - ref) * scale);
            int pos = nsel + __popc(sbal & lmask);
            si[pos] = i; sw[pos] = w;
            dsum += w;
        }
        neq  += __popc(ebal);
        nsel += __popc(sbal);
    }
    #pragma unroll
    for (int o = 16; o > 0; o >>= 1) dsum += __shfl_xor_sync(FULL, dsum, o);
    const float inv = 1.f / dsum;

    // ---- Phase 3: PV gather (float2 per lane, 4-way MLP) ----
    const float2* V2 = (const float2*)Vb;   // row stride = 32 float2
    float ax = 0.f, ay = 0.f;
    const int S = nsel;
    int t = 0;
    for (; t + 4 <= S; t += 4) {
        int i0 = si[t], i1 = si[t + 1], i2 = si[t + 2], i3 = si[t + 3];
        float w0 = sw[t], w1 = sw[t + 1], w2 = sw[t + 2], w3 = sw[t + 3];
        float2 v0 = V2[(size_t)i0 * 32 + lane];
        float2 v1 = V2[(size_t)i1 * 32 + lane];
        float2 v2 = V2[(size_t)i2 * 32 + lane];
        float2 v3 = V2[(size_t)i3 * 32 + lane];
        ax = fmaf(w0, v0.x, ax); ay = fmaf(w0, v0.y, ay);
        ax = fmaf(w1, v1.x, ax); ay = fmaf(w1, v1.y, ay);
        ax = fmaf(w2, v2.x, ax); ay = fmaf(w2, v2.y, ay);
        ax = fmaf(w3, v3.x, ax); ay = fmaf(w3, v3.y, ay);
    }
    for (; t < S; t++) {
        int i0 = si[t]; float w0 = sw[t];
        float2 v0 = V2[(size_t)i0 * 32 + lane];
        ax = fmaf(w0, v0.x, ax); ay = fmaf(w0, v0.y, ay);
    }

    float2* orow = (float2*)(Og + ((size_t)bh * SL + qg) * HD);
    orow[lane] = make_float2(ax * inv, ay * inv);
}

extern "C" void kernel_launch(void* const* d_in, const int* in_sizes, int n_in,
                              void* d_out, int out_size) {
    (void)in_sizes; (void)n_in; (void)out_size;
    const float* Q = (const float*)d_in[0];
    const float* K = (const float*)d_in[1];
    const float* V = (const float*)d_in[2];
    float* O = (float*)d_out;

    cudaFuncSetAttribute(topk_attn_kernel,
                         cudaFuncAttributeMaxDynamicSharedMemorySize, SM_TOTAL);

    dim3 grid(SL / TQ, NB * NH);   // (128, 64)
    topk_attn_kernel<<<grid, NTHR, SM_TOTAL>>>(Q, K, V, O);
}

// round 5
// speedup vs baseline: 1.3396x; 1.3396x over previous
#include <cuda_runtime.h>
#include <cstdint>

// Problem constants
#define NB 4
#define NH 16
#define SL 2048
#define HD 64
#define TOPKK 128

// Tiling
#define TQ 8       // queries per CTA
#define CK 128     // key chunk
#define NTHR 256
#define WCAP 767   // wb[0..766] bucket, wb[767] counter, wb[768..1023] hist(256)

// SMEM layout (bytes) — 108544 per CTA, 2 CTAs/SM
#define SM_KEYS  0
#define SM_QS    (TQ*SL*4)               // 65536
#define SM_KS    (SM_QS + TQ*HD*4)       // 67584
#define SM_SELI  (SM_KS + CK*HD*4)       // 100352
#define SM_SELW  (SM_SELI + TQ*TOPKK*4)  // 104448
#define SM_TOTAL (SM_SELW + TQ*TOPKK*4)  // 108544

#define NEGMAX -3.402823466e38f

// order-preserving float -> uint key (monotone increasing)
__device__ __forceinline__ uint32_t f2k(float f) {
    uint32_t b = __float_as_uint(f);
    return b ^ (0x80000000u | (uint32_t)((int32_t)b >> 31));
}
__device__ __forceinline__ float k2f(uint32_t k) {
    uint32_t b = k ^ ((k >> 31) ? 0x80000000u : 0xFFFFFFFFu);
    return __uint_as_float(b);
}

// descending bin scan: given hist[256] and rank r (1-based from the top),
// return bin B containing rank r; update r to the rank within bin B.
__device__ __forceinline__ void bin_scan(const uint32_t* hist, int lane, int& r, int& B) {
    const unsigned FULL = 0xFFFFFFFFu;
    int rev[8]; int s = 0;
    #pragma unroll
    for (int t = 0; t < 8; t++) { rev[t] = (int)hist[255 - (lane * 8 + t)]; s += rev[t]; }
    int inc = s;
    #pragma unroll
    for (int o = 1; o < 32; o <<= 1) {
        int v = __shfl_up_sync(FULL, inc, o);
        if (lane >= o) inc += v;
    }
    int pre = inc - s;          // count in bins strictly above this lane's bins
    int cum = pre, Bl = -1, rsub = 0;
    #pragma unroll
    for (int t = 0; t < 8; t++) {
        cum += rev[t];
        if (Bl < 0 && cum >= r) { Bl = 255 - (lane * 8 + t); rsub = r - (cum - rev[t]); }
    }
    unsigned bal = __ballot_sync(FULL, Bl >= 0);
    int src = __ffs(bal) - 1;
    B = __shfl_sync(FULL, Bl, src);
    r = __shfl_sync(FULL, rsub, src);
}

__global__ void __launch_bounds__(NTHR, 2)
topk_attn_kernel(const float* __restrict__ Qg, const float* __restrict__ Kg,
                 const float* __restrict__ Vg, float* __restrict__ Og)
{
    extern __shared__ char smem[];
    uint32_t* keys = (uint32_t*)(smem + SM_KEYS);   // [TQ][SL]
    float4*   Qs4  = (float4*)(smem + SM_QS);       // [TQ][16] swizzled
    float4*   Ks4  = (float4*)(smem + SM_KS);       // [CK][16] swizzled
    int*      seli = (int*)(smem + SM_SELI);
    float*    selw = (float*)(smem + SM_SELW);

    const int qt  = (gridDim.x - 1) - blockIdx.x;   // heavy tiles first
    const int bh  = blockIdx.y;
    const int tid = threadIdx.x;
    const int qbase  = qt * TQ;
    const int kneed  = qbase + TQ;
    const int nchunk = (kneed + CK - 1) / CK;

    const float* Qb = Qg + ((size_t)bh * SL + qbase) * HD;
    const float* Kb = Kg + (size_t)bh * SL * HD;
    const float* Vb = Vg + (size_t)bh * SL * HD;

    // ---- stage Q tile (swizzled col ^= row&7) ----
    if (tid < TQ * 16) {
        int q = tid >> 4, c = tid & 15;
        Qs4[q * 16 + (c ^ (q & 7))] = ((const float4*)(Qb + q * HD))[c];
    }
    __syncthreads();

    // ---- Phase 1: QK^T, scalar fmaf, 2q x 2k per lane ----
    const int qp = tid & 3;            // q-pair 0..3 -> queries 2qp, 2qp+1
    const int kg = tid >> 2;           // 0..63 -> keys 2kg, 2kg+1
    const int qr0 = 2 * qp, qr1 = 2 * qp + 1;
    const int kr0 = 2 * kg, kr1 = 2 * kg + 1;
    const int qs0 = qr0 & 7, qs1 = qr1 & 7;
    const int ks  = kg & 7;            // (2kg>>1)&7 == ((2kg+1)>>1)&7 == kg&7

    for (int ch = 0; ch < nchunk; ch++) {
        const int kbase = ch * CK;
        // stage K chunk: 2048 float4 / 256 threads = 8 iters (swizzle col ^= (row>>1)&7)
        #pragma unroll
        for (int it = 0; it < 8; it++) {
            int idx = it * NTHR + tid;
            int r = idx >> 4, c = idx & 15;
            Ks4[r * 16 + (c ^ ((r >> 1) & 7))] =
                ((const float4*)(Kb + (size_t)(kbase + r) * HD))[c];
        }
        __syncthreads();

        float a00 = 0.f, a01 = 0.f, a10 = 0.f, a11 = 0.f;
        #pragma unroll
        for (int d4 = 0; d4 < 16; d4++) {
            float4 q0 = Qs4[qr0 * 16 + (d4 ^ qs0)];
            float4 q1 = Qs4[qr1 * 16 + (d4 ^ qs1)];
            float4 k0 = Ks4[kr0 * 16 + (d4 ^ ks)];
            float4 k1 = Ks4[kr1 * 16 + (d4 ^ ks)];
            a00 = fmaf(q0.x, k0.x, a00); a00 = fmaf(q0.y, k0.y, a00);
            a00 = fmaf(q0.z, k0.z, a00); a00 = fmaf(q0.w, k0.w, a00);
            a01 = fmaf(q0.x, k1.x, a01); a01 = fmaf(q0.y, k1.y, a01);
            a01 = fmaf(q0.z, k1.z, a01); a01 = fmaf(q0.w, k1.w, a01);
            a10 = fmaf(q1.x, k0.x, a10); a10 = fmaf(q1.y, k0.y, a10);
            a10 = fmaf(q1.z, k0.z, a10); a10 = fmaf(q1.w, k0.w, a10);
            a11 = fmaf(q1.x, k1.x, a11); a11 = fmaf(q1.y, k1.y, a11);
            a11 = fmaf(q1.z, k1.z, a11); a11 = fmaf(q1.w, k1.w, a11);
        }
        const int k0i = kbase + 2 * kg;
        {
            int qgl = qbase + qr0;
            uint2 st;
            st.x = f2k((k0i     <= qgl) ? a00 : NEGMAX);
            st.y = f2k((k0i + 1 <= qgl) ? a01 : NEGMAX);
            *(uint2*)&keys[qr0 * SL + k0i] = st;
        }
        {
            int qgl = qbase + qr1;
            uint2 st;
            st.x = f2k((k0i     <= qgl) ? a10 : NEGMAX);
            st.y = f2k((k0i + 1 <= qgl) ? a11 : NEGMAX);
            *(uint2*)&keys[qr1 * SL + k0i] = st;
        }
        __syncthreads();
    }

    // ---- Phase 2: histogram radix top-128 (one warp per query) ----
    const int warp = tid >> 5, lane = tid & 31;
    const unsigned FULL = 0xFFFFFFFFu;
    const uint32_t lmask = (1u << lane) - 1u;
    const float scale = 0.125f;

    const int qi = warp;
    const int qg = qbase + qi;
    const int n  = qg + 1;
    uint32_t* krow = keys + qi * SL;
    const uint4* kr4 = (const uint4*)krow;
    const int nv4 = n >> 2;

    uint32_t* wb   = (uint32_t*)(smem + SM_KS) + warp * 1024;
    uint32_t* hist = wb + 768;

    uint32_t T = 0; int need_eq = 0;

    if (n > TOPKK) {
        // L1: histogram of byte3 (warp-aggregated atomics via match_any)
        #pragma unroll
        for (int t = 0; t < 8; t++) hist[lane + 32 * t] = 0;
        __syncwarp();
        for (int base = 0; base < nv4; base += 32) {
            int i = base + lane; bool v = i < nv4;
            uint4 x = v ? kr4[i] : make_uint4(0, 0, 0, 0);
            uint32_t b;
            #pragma unroll
            for (int c = 0; c < 4; c++) {
                uint32_t kk = (c == 0) ? x.x : (c == 1) ? x.y : (c == 2) ? x.z : x.w;
                b = v ? (kk >> 24) : 0xFFFFFFFFu;
                unsigned grp = __match_any_sync(FULL, b);
                if (v && lane == __ffs(grp) - 1) atomicAdd(&hist[b], __popc(grp));
            }
        }
        for (int base = nv4 << 2; base < n; base += 32) {
            int i = base + lane; bool v = i < n;
            uint32_t b = v ? (krow[i] >> 24) : 0xFFFFFFFFu;
            unsigned grp = __match_any_sync(FULL, b);
            if (v && lane == __ffs(grp) - 1) atomicAdd(&hist[b], __popc(grp));
        }
        __syncwarp();
        int r = TOPKK, B;
        bin_scan(hist, lane, r, B);

        // L2: compact bucket B into wb while histogramming byte2
        #pragma unroll
        for (int t = 0; t < 8; t++) hist[lane + 32 * t] = 0;
        __syncwarp();
        int m = 0;
        for (int base = 0; base < n; base += 32) {
            int i = base + lane;
            uint32_t k = (i < n) ? krow[i] : 0u;
            bool mt = (i < n) && ((int)(k >> 24) == B);
            unsigned bal = __ballot_sync(FULL, mt);
            int pos = m + __popc(bal & lmask);
            if (mt) {
                if (pos < WCAP) wb[pos] = k;
                atomicAdd(&hist[(k >> 16) & 255u], 1);
            }
            m += __popc(bal);
        }
        __syncwarp();

        uint32_t prefix = ((uint32_t)B) << 24;
        if (m <= WCAP) {
            int B2;
            bin_scan(hist, lane, r, B2);
            prefix |= ((uint32_t)B2) << 16;
            // compact wb to byte2 match (in place)
            int m2 = 0;
            for (int base = 0; base < m; base += 32) {
                int i = base + lane;
                uint32_t k = (i < m) ? wb[i] : 0u;
                bool mt = (i < m) && ((int)((k >> 16) & 255u) == B2);
                unsigned bal = __ballot_sync(FULL, mt);
                int pos = m2 + __popc(bal & lmask);
                __syncwarp();
                if (mt) wb[pos] = k;
                m2 += __popc(bal);
            }
            __syncwarp();
            // final 16 bits
            if (m2 <= 32) {
                uint32_t e = (lane < m2) ? wb[lane] : 0u;
                bool has = lane < m2;
                #pragma unroll
                for (int b = 15; b >= 0; b--) {
                    uint32_t test = prefix | (1u << b);
                    uint32_t hm = ~((1u << b) - 1u);
                    int c = __popc(__ballot_sync(FULL, has && ((e & hm) == test)));
                    if (c >= r) prefix = test; else r -= c;
                }
            } else {
                #pragma unroll 1
                for (int b = 15; b >= 0; b--) {
                    uint32_t bit = 1u << b;
                    int c = 0;
                    for (int i = lane; i < m2; i += 32) c += ((wb[i] & bit) != 0);
                    c = __reduce_add_sync(FULL, c);
                    bool keep = (c >= r);
                    if (!keep) r -= c;
                    int nm = 0;
                    for (int base = 0; base < m2; base += 32) {
                        int i = base + lane;
                        uint32_t k = (i < m2) ? wb[i] : 0u;
                        bool kp = (i < m2) && (((k & bit) != 0) == keep);
                        unsigned bal = __ballot_sync(FULL, kp);
                        int pos = nm + __popc(bal & lmask);
                        __syncwarp();
                        if (kp) wb[pos] = k;
                        nm += __popc(bal);
                    }
                    m2 = nm;
                    if (keep) prefix |= bit;
                    __syncwarp();
                }
            }
        } else {
            // rare fallback: full-row descent on the remaining 24 bits
            #pragma unroll 1
            for (int b = 23; b >= 0; b--) {
                uint32_t test = prefix | (1u << b);
                uint32_t hm = ~((1u << b) - 1u);
                int c = 0;
                for (int base = 0; base < nv4; base += 32) {
                    int i = base + lane;
                    if (i < nv4) {
                        uint4 v = kr4[i];
                        c += ((v.x & hm) == test) + ((v.y & hm) == test)
                           + ((v.z & hm) == test) + ((v.w & hm) == test);
                    }
                }
                for (int i = (nv4 << 2) + lane; i < n; i += 32)
                    c += ((krow[i] & hm) == test);
                c = __reduce_add_sync(FULL, c);
                if (c >= r) prefix = test; else r -= c;
            }
        }
        T = prefix; need_eq = r;
    }

    // ---- weight pass: atomic-append selected (order-free), then ordered ties ----
    const float ref = (n > TOPKK) ? k2f(T) : 0.0f;
    int* si = seli + qi * TOPKK;
    float* sw = selw + qi * TOPKK;
    uint32_t* cnt = wb + 767;
    if (lane == 0) *cnt = 0;
    __syncwarp();

    float dsum = 0.f;
    for (int base = 0; base < nv4; base += 32) {
        int i = base + lane;
        if (i < nv4) {
            uint4 x = kr4[i];
            #pragma unroll
            for (int c = 0; c < 4; c++) {
                uint32_t k = (c == 0) ? x.x : (c == 1) ? x.y : (c == 2) ? x.z : x.w;
                if (k > T) {
                    float w = __expf((k2f(k) - ref) * scale);
                    int p = atomicAdd(cnt, 1);
                    si[p] = 4 * i + c; sw[p] = w;
                    dsum += w;
                }
            }
        }
    }
    for (int i = (nv4 << 2) + lane; i < n; i += 32) {
        uint32_t k = krow[i];
        if (k > T) {
            float w = __expf((k2f(k) - ref) * scale);
            int p = atomicAdd(cnt, 1);
            si[p] = i; sw[p] = w;
            dsum += w;
        }
    }
    if (need_eq > 0) {   // ties at T: lowest indices first (matches jax top_k)
        int neq = 0;
        for (int base = 0; base < n && neq < need_eq; base += 32) {
            int i = base + lane;
            uint32_t k = (i < n) ? krow[i] : 0u;
            bool eq = (i < n) && (k == T);
            unsigned ebal = __ballot_sync(FULL, eq);
            bool sel = eq && (neq + __popc(ebal & lmask)) < need_eq;
            if (sel) {
                int p = atomicAdd(cnt, 1);
                si[p] = i; sw[p] = 1.0f;   // exp(0)
                dsum += 1.0f;
            }
            neq += __popc(ebal);
        }
    }
    #pragma unroll
    for (int o = 16; o > 0; o >>= 1) dsum += __shfl_xor_sync(FULL, dsum, o);
    const float inv = 1.f / dsum;
    __syncwarp();

    // ---- Phase 3: PV gather (float2 per lane, 8-way MLP) ----
    const float2* V2 = (const float2*)Vb;     // row stride = 32 float2
    const int S = (n > TOPKK) ? TOPKK : n;
    float ax = 0.f, ay = 0.f;
    int t = 0;
    for (; t + 8 <= S; t += 8) {
        int   ii[8]; float ww[8]; float2 vv[8];
        #pragma unroll
        for (int u = 0; u < 8; u++) { ii[u] = si[t + u]; ww[u] = sw[t + u]; }
        #pragma unroll
        for (int u = 0; u < 8; u++) vv[u] = V2[(size_t)ii[u] * 32 + lane];
        #pragma unroll
        for (int u = 0; u < 8; u++) {
            ax = fmaf(ww[u], vv[u].x, ax);
            ay = fmaf(ww[u], vv[u].y, ay);
        }
    }
    for (; t < S; t++) {
        float w = sw[t];
        float2 v = V2[(size_t)si[t] * 32 + lane];
        ax = fmaf(w, v.x, ax); ay = fmaf(w, v.y, ay);
    }

    float2* orow = (float2*)(Og + ((size_t)bh * SL + qg) * HD);
    orow[lane] = make_float2(ax * inv, ay * inv);
}

extern "C" void kernel_launch(void* const* d_in, const int* in_sizes, int n_in,
                              void* d_out, int out_size) {
    (void)in_sizes; (void)n_in; (void)out_size;
    const float* Q = (const float*)d_in[0];
    const float* K = (const float*)d_in[1];
    const float* V = (const float*)d_in[2];
    float* O = (float*)d_out;

    cudaFuncSetAttribute(topk_attn_kernel,
                         cudaFuncAttributeMaxDynamicSharedMemorySize, SM_TOTAL);

    dim3 grid(SL / TQ, NB * NH);   // (256, 64)
    topk_attn_kernel<<<grid, NTHR, SM_TOTAL>>>(Q, K, V, O);
}

// round 7
// speedup vs baseline: 2.2687x; 1.6936x over previous
#include <cuda_runtime.h>
#include <cstdint>

// Problem constants
#define NB 4
#define NH 16
#define SL 2048
#define HD 64
#define TOPKK 128
#define NEGMAX -3.402823466e38f

// 1 GiB score-key scratch: [bh][q][k]
__device__ uint32_t g_keys[(size_t)NB * NH * SL * SL];

// order-preserving float <-> uint key (monotone increasing)
__device__ __forceinline__ uint32_t f2k(float f) {
    uint32_t b = __float_as_uint(f);
    return b ^ (0x80000000u | (uint32_t)((int32_t)b >> 31));
}
__device__ __forceinline__ float k2f(uint32_t k) {
    uint32_t b = k ^ ((k >> 31) ? 0x80000000u : 0xFFFFFFFFu);
    return __uint_as_float(b);
}

// ============================================================
// Kernel A: causal QK^T -> score keys (128x128 tiles, 8x8/thread)
// ============================================================
#define TILE 128
#define APAD 132           // smem row stride (floats); mult of 4 -> float4-aligned rows
#define A_SMEM (2 * 64 * APAD * 4)   // 67584 bytes

__global__ void __launch_bounds__(256, 2)
qk_kernel(const float* __restrict__ Qg, const float* __restrict__ Kg)
{
    extern __shared__ float sm[];
    float* Qs = sm;                 // [64][APAD] transposed: Qs[d][q]
    float* Ks = sm + 64 * APAD;     // [64][APAD] transposed: Ks[d][k]

    // decode lower-triangle tile (heavy tiles first)
    int t = (gridDim.x - 1) - blockIdx.x;
    int qt = (int)((sqrtf(8.f * (float)t + 1.f) - 1.f) * 0.5f);
    while ((qt + 1) * (qt + 2) / 2 <= t) qt++;
    while (qt * (qt + 1) / 2 > t) qt--;
    int kt = t - qt * (qt + 1) / 2;

    const int bh = blockIdx.y;
    const int qbase = qt * TILE, kbase = kt * TILE;
    const int tid = threadIdx.x;

    const float* Qp = Qg + ((size_t)bh * SL + qbase) * HD;
    const float* Kp = Kg + ((size_t)bh * SL + kbase) * HD;

    // stage both tiles transposed (coalesced LDG.128)
    #pragma unroll
    for (int it = 0; it < 8; it++) {
        int idx = it * 256 + tid;        // 0..2047
        int r = idx >> 4, c = idx & 15;  // row, float4 col
        float4 v = ((const float4*)(Qp + (size_t)r * HD))[c];
        Qs[(4 * c + 0) * APAD + r] = v.x; Qs[(4 * c + 1) * APAD + r] = v.y;
        Qs[(4 * c + 2) * APAD + r] = v.z; Qs[(4 * c + 3) * APAD + r] = v.w;
        float4 w = ((const float4*)(Kp + (size_t)r * HD))[c];
        Ks[(4 * c + 0) * APAD + r] = w.x; Ks[(4 * c + 1) * APAD + r] = w.y;
        Ks[(4 * c + 2) * APAD + r] = w.z; Ks[(4 * c + 3) * APAD + r] = w.w;
    }
    __syncthreads();

    const int tx = tid & 15, ty = tid >> 4;
    const int q0 = ty * 8, k0 = tx * 8;

    float acc[8][8] = {};
    #pragma unroll 4
    for (int d = 0; d < 64; d++) {
        float a[8], b[8];
        *(float4*)&a[0] = *(const float4*)&Qs[d * APAD + q0];
        *(float4*)&a[4] = *(const float4*)&Qs[d * APAD + q0 + 4];
        *(float4*)&b[0] = *(const float4*)&Ks[d * APAD + k0];
        *(float4*)&b[4] = *(const float4*)&Ks[d * APAD + k0 + 4];
        #pragma unroll
        for (int i = 0; i < 8; i++)
            #pragma unroll
            for (int j = 0; j < 8; j++)
                acc[i][j] = fmaf(a[i], b[j], acc[i][j]);
    }

    const bool diag = (qt == kt);
    #pragma unroll
    for (int i = 0; i < 8; i++) {
        const int qg = qbase + q0 + i;
        uint32_t* row = g_keys + ((size_t)bh * SL + qg) * SL + kbase + k0;
        uint4 lo, hi;
        if (diag) {
            int ql = q0 + i;
            lo.x = f2k((k0     <= ql) ? acc[i][0] : NEGMAX);
            lo.y = f2k((k0 + 1 <= ql) ? acc[i][1] : NEGMAX);
            lo.z = f2k((k0 + 2 <= ql) ? acc[i][2] : NEGMAX);
            lo.w = f2k((k0 + 3 <= ql) ? acc[i][3] : NEGMAX);
            hi.x = f2k((k0 + 4 <= ql) ? acc[i][4] : NEGMAX);
            hi.y = f2k((k0 + 5 <= ql) ? acc[i][5] : NEGMAX);
            hi.z = f2k((k0 + 6 <= ql) ? acc[i][6] : NEGMAX);
            hi.w = f2k((k0 + 7 <= ql) ? acc[i][7] : NEGMAX);
        } else {
            lo.x = f2k(acc[i][0]); lo.y = f2k(acc[i][1]);
            lo.z = f2k(acc[i][2]); lo.w = f2k(acc[i][3]);
            hi.x = f2k(acc[i][4]); hi.y = f2k(acc[i][5]);
            hi.z = f2k(acc[i][6]); hi.w = f2k(acc[i][7]);
        }
        *(uint4*)row = lo;
        *(uint4*)(row + 4) = hi;
    }
}

// ============================================================
// Kernel B: exact top-128 select + softmax + PV gather
// ============================================================
#define WCAP 576
// per-warp u32 layout: hist 256 | wbk 576 | wbi 576 | seli 128 | selw 128 = 1664
#define WSTRIDE 1664
#define B_SMEM (8 * WSTRIDE * 4)

// descending bin scan: hist[256], rank r (1-based from top) -> bin B, r = rank in B
__device__ __forceinline__ void bin_scan(const uint32_t* hist, int lane, int& r, int& B) {
    const unsigned FULL = 0xFFFFFFFFu;
    int rev[8]; int s = 0;
    #pragma unroll
    for (int t = 0; t < 8; t++) { rev[t] = (int)hist[255 - (lane * 8 + t)]; s += rev[t]; }
    int inc = s;
    #pragma unroll
    for (int o = 1; o < 32; o <<= 1) {
        int v = __shfl_up_sync(FULL, inc, o);
        if (lane >= o) inc += v;
    }
    int pre = inc - s;
    int cum = pre, Bl = -1, rsub = 0;
    #pragma unroll
    for (int t = 0; t < 8; t++) {
        cum += rev[t];
        if (Bl < 0 && cum >= r) { Bl = 255 - (lane * 8 + t); rsub = r - (cum - rev[t]); }
    }
    unsigned bal = __ballot_sync(FULL, Bl >= 0);
    int src = __ffs(bal) - 1;
    B = __shfl_sync(FULL, Bl, src);
    r = __shfl_sync(FULL, rsub, src);
}

__global__ void __launch_bounds__(256)
sel_kernel(const float* __restrict__ Vg, float* __restrict__ Og)
{
    extern __shared__ uint32_t smb[];
    const int tid = threadIdx.x;
    const int warp = tid >> 5, lane = tid & 31;
    const unsigned FULL = 0xFFFFFFFFu;
    const uint32_t lmask = (1u << lane) - 1u;
    const float scale = 0.125f;   // 64^-0.5

    uint32_t* wmem = smb + warp * WSTRIDE;
    uint32_t* hist = wmem;
    uint32_t* wbk  = wmem + 256;
    uint32_t* wbi  = wmem + 256 + WCAP;
    int*      seli = (int*)(wmem + 256 + 2 * WCAP);
    float*    selw = (float*)(wmem + 256 + 2 * WCAP + 128);

    const int bh = blockIdx.y;
    const int qg = blockIdx.x * 8 + warp;
    const int n  = qg + 1;
    const uint32_t* krow = g_keys + ((size_t)bh * SL + qg) * SL;
    const uint4* kr4 = (const uint4*)krow;
    const int nv4 = n >> 2;

    int nsel = 0;
    float dsum = 0.f;
    float ref = 0.f;

    if (n > TOPKK) {
        // ---- scan 1: byte3 histogram (warp-aggregated smem atomics) ----
        #pragma unroll
        for (int t = 0; t < 8; t++) hist[lane + 32 * t] = 0;
        __syncwarp();
        for (int base = 0; base < nv4; base += 32) {
            int i = base + lane; bool v = i < nv4;
            uint4 x = v ? kr4[i] : make_uint4(0, 0, 0, 0);
            #pragma unroll
            for (int c = 0; c < 4; c++) {
                uint32_t kk = (c == 0) ? x.x : (c == 1) ? x.y : (c == 2) ? x.z : x.w;
                uint32_t b = v ? (kk >> 24) : 0xFFFFFFFFu;
                unsigned grp = __match_any_sync(FULL, b);
                if (v && lane == __ffs(grp) - 1) atomicAdd(&hist[b], __popc(grp));
            }
        }
        for (int base = nv4 << 2; base < n; base += 32) {
            int i = base + lane; bool v = i < n;
            uint32_t b = v ? (krow[i] >> 24) : 0xFFFFFFFFu;
            unsigned grp = __match_any_sync(FULL, b);
            if (v && lane == __ffs(grp) - 1) atomicAdd(&hist[b], __popc(grp));
        }
        __syncwarp();
        int r = TOPKK, B;
        bin_scan(hist, lane, r, B);

        ref = k2f(((uint32_t)B) << 24);   // softmax shift reference (bin base)

        // ---- scan 2: append sure (byte3 > B) w/ weights; compact bin B; byte2 hist ----
        #pragma unroll
        for (int t = 0; t < 8; t++) hist[lane + 32 * t] = 0;
        __syncwarp();
        int m = 0;
        for (int base = 0; base < n; base += 32) {
            int i = base + lane;
            uint32_t k = (i < n) ? krow[i] : 0u;
            int b3 = (int)(k >> 24);
            bool sure = (i < n) && (b3 > B);
            bool inb  = (i < n) && (b3 == B);
            unsigned sbal = __ballot_sync(FULL, sure);
            unsigned bbal = __ballot_sync(FULL, inb);
            if (sure) {
                float w = __expf((k2f(k) - ref) * scale);
                int p = nsel + __popc(sbal & lmask);
                seli[p] = i; selw[p] = w; dsum += w;
            }
            if (inb) {
                int p = m + __popc(bbal & lmask);
                if (p < WCAP) { wbk[p] = k; wbi[p] = (uint32_t)i; }
                atomicAdd(&hist[(k >> 16) & 255u], 1);
            }
            nsel += __popc(sbal);
            m    += __popc(bbal);
        }
        __syncwarp();

        uint32_t T; int need_eq;
        uint32_t prefix = ((uint32_t)B) << 24;

        if (m <= WCAP) {
            int B2;
            bin_scan(hist, lane, r, B2);
            // bucket pass: append sure (byte2 > B2), compact (== B2) to front
            int m2 = 0;
            for (int base = 0; base < m; base += 32) {
                int i = base + lane;
                uint32_t k = 0, idx = 0;
                if (i < m) { k = wbk[i]; idx = wbi[i]; }
                int b2 = (int)((k >> 16) & 255u);
                bool sure = (i < m) && (b2 > B2);
                bool inb  = (i < m) && (b2 == B2);
                unsigned sbal = __ballot_sync(FULL, sure);
                unsigned bbal = __ballot_sync(FULL, inb);
                if (sure) {
                    float w = __expf((k2f(k) - ref) * scale);
                    int p = nsel + __popc(sbal & lmask);
                    seli[p] = (int)idx; selw[p] = w; dsum += w;
                }
                if (inb) {
                    int p = m2 + __popc(bbal & lmask);
                    wbk[p] = k; wbi[p] = idx;
                }
                nsel += __popc(sbal);
                m2   += __popc(bbal);
            }
            __syncwarp();
            prefix |= ((uint32_t)B2) << 16;

            // final 16 bits on the small set
            if (m2 <= 32) {
                uint32_t e = (lane < m2) ? wbk[lane] : 0u;
                bool has = lane < m2;
                #pragma unroll
                for (int b = 15; b >= 0; b--) {
                    uint32_t test = prefix | (1u << b);
                    uint32_t hm = ~((1u << b) - 1u);
                    int c = __popc(__ballot_sync(FULL, has && ((e & hm) == test)));
                    if (c >= r) prefix = test; else r -= c;
                }
            } else {
                #pragma unroll 1
                for (int b = 15; b >= 0 && m2 > 1; b--) {
                    uint32_t bit = 1u << b;
                    int c = 0;
                    for (int i = lane; i < m2; i += 32) c += ((wbk[i] & bit) != 0);
                    c = __reduce_add_sync(FULL, c);
                    bool keep = (c >= r);
                    if (!keep) r -= c;
                    int nm = 0;
                    for (int base = 0; base < m2; base += 32) {
                        int i = base + lane;
                        uint32_t k = 0, idx = 0;
                        if (i < m2) { k = wbk[i]; idx = wbi[i]; }
                        bool kp = (i < m2) && (((k & bit) != 0) == keep);
                        unsigned bal = __ballot_sync(FULL, kp);
                        int p = nm + __popc(bal & lmask);
                        if (kp) { wbk[p] = k; wbi[p] = idx; }
                        nm += __popc(bal);
                    }
                    m2 = nm;
                    if (keep) prefix |= bit;
                    __syncwarp();
                }
                if (m2 == 1) prefix = wbk[0];
            }
            T = prefix; need_eq = r;

            // select remainder from compacted bucket (index order preserved)
            int neq = 0;
            const float tw = __expf((k2f(T) - ref) * scale);
            for (int base = 0; base < m2; base += 32) {
                int i = base + lane;
                uint32_t k = 0, idx = 0;
                if (i < m2) { k = wbk[i]; idx = wbi[i]; }
                bool gt = (i < m2) && (k > T);
                bool eq = (i < m2) && (k == T);
                unsigned ebal = __ballot_sync(FULL, eq);
                bool sel = gt || (eq && (neq + __popc(ebal & lmask)) < need_eq);
                unsigned sbal = __ballot_sync(FULL, sel);
                if (sel) {
                    float w = eq ? tw : __expf((k2f(k) - ref) * scale);
                    int p = nsel + __popc(sbal & lmask);
                    seli[p] = (int)idx; selw[p] = w; dsum += w;
                }
                neq  += __popc(ebal);
                nsel += __popc(sbal);
            }
        } else {
            // rare fallback: bucket overflow -> full-row descent on low 24 bits
            #pragma unroll 1
            for (int b = 23; b >= 0; b--) {
                uint32_t test = prefix | (1u << b);
                uint32_t hm = ~((1u << b) - 1u);
                int c = 0;
                for (int base = 0; base < nv4; base += 32) {
                    int i = base + lane;
                    if (i < nv4) {
                        uint4 v = kr4[i];
                        c += ((v.x & hm) == test) + ((v.y & hm) == test)
                           + ((v.z & hm) == test) + ((v.w & hm) == test);
                    }
                }
                for (int i = (nv4 << 2) + lane; i < n; i += 32)
                    c += ((krow[i] & hm) == test);
                c = __reduce_add_sync(FULL, c);
                if (c >= r) prefix = test; else r -= c;
            }
            T = prefix; need_eq = r;
            // rescan row for bin-B elements > T, plus ordered ties == T
            int neq = 0;
            const float tw = __expf((k2f(T) - ref) * scale);
            for (int base = 0; base < n; base += 32) {
                int i = base + lane;
                uint32_t k = (i < n) ? krow[i] : 0u;
                bool inb = (i < n) && ((int)(k >> 24) == (int)(T >> 24));
                bool gt = inb && (k > T);
                bool eq = inb && (k == T);
                unsigned ebal = __ballot_sync(FULL, eq);
                bool sel = gt || (eq && (neq + __popc(ebal & lmask)) < need_eq);
                unsigned sbal = __ballot_sync(FULL, sel);
                if (sel) {
                    float w = eq ? tw : __expf((k2f(k) - ref) * scale);
                    int p = nsel + __popc(sbal & lmask);
                    seli[p] = i; selw[p] = w; dsum += w;
                }
                neq  += __popc(ebal);
                nsel += __popc(sbal);
            }
        }
    } else {
        // n <= 128: select all (ref = 0)
        for (int base = 0; base < n; base += 32) {
            int i = base + lane;
            bool v = i < n;
            unsigned bal = __ballot_sync(FULL, v);
            if (v) {
                float w = __expf(k2f(krow[i]) * scale);
                int p = nsel + __popc(bal & lmask);
                seli[p] = i; selw[p] = w; dsum += w;
            }
            nsel += __popc(bal);
        }
    }

    #pragma unroll
    for (int o = 16; o > 0; o >>= 1) dsum += __shfl_xor_sync(FULL, dsum, o);
    const float inv = 1.f / dsum;
    __syncwarp();

    // ---- PV gather: float2 per lane, 8-deep MLP ----
    const float2* V2 = (const float2*)(Vg + (size_t)bh * SL * HD);
    const int S = nsel;
    float ax = 0.f, ay = 0.f;
    int t = 0;
    for (; t + 8 <= S; t += 8) {
        int ii[8]; float ww[8]; float2 vv[8];
        #pragma unroll
        for (int u = 0; u < 8; u++) { ii[u] = seli[t + u]; ww[u] = selw[t + u]; }
        #pragma unroll
        for (int u = 0; u < 8; u++) vv[u] = V2[(size_t)ii[u] * 32 + lane];
        #pragma unroll
        for (int u = 0; u < 8; u++) {
            ax = fmaf(ww[u], vv[u].x, ax);
            ay = fmaf(ww[u], vv[u].y, ay);
        }
    }
    for (; t < S; t++) {
        float w = selw[t];
        float2 v = V2[(size_t)seli[t] * 32 + lane];
        ax = fmaf(w, v.x, ax); ay = fmaf(w, v.y, ay);
    }

    float2* orow = (float2*)(Og + ((size_t)bh * SL + qg) * HD);
    orow[lane] = make_float2(ax * inv, ay * inv);
}

// ============================================================
extern "C" void kernel_launch(void* const* d_in, const int* in_sizes, int n_in,
                              void* d_out, int out_size) {
    (void)in_sizes; (void)n_in; (void)out_size;
    const float* Q = (const float*)d_in[0];
    const float* K = (const float*)d_in[1];
    const float* V = (const float*)d_in[2];
    float* O = (float*)d_out;

    cudaFuncSetAttribute(qk_kernel,  cudaFuncAttributeMaxDynamicSharedMemorySize, A_SMEM);
    cudaFuncSetAttribute(sel_kernel, cudaFuncAttributeMaxDynamicSharedMemorySize, B_SMEM);

    const int ntiles = (SL / TILE) * (SL / TILE + 1) / 2;   // 136
    dim3 gridA(ntiles, NB * NH);
    qk_kernel<<<gridA, 256, A_SMEM>>>(Q, K);

    dim3 gridB(SL / 8, NB * NH);    // (256, 64)
    sel_kernel<<<gridB, 256, B_SMEM>>>(V, O);
}

// round 9
// speedup vs baseline: 2.4262x; 1.0694x over previous
#include <cuda_runtime.h>
#include <cstdint>

// Problem constants
#define NB 4
#define NH 16
#define SL 2048
#define HD 64
#define TOPKK 128
#define NEGMAX -3.402823466e38f

typedef unsigned long long u64;

// 1 GiB score-key scratch: [bh][q][k]
__device__ uint32_t g_keys[(size_t)NB * NH * SL * SL];

// order-preserving float <-> uint key (monotone increasing)
__device__ __forceinline__ uint32_t f2k(float f) {
    uint32_t b = __float_as_uint(f);
    return b ^ (0x80000000u | (uint32_t)((int32_t)b >> 31));
}
__device__ __forceinline__ float k2f(uint32_t k) {
    uint32_t b = k ^ ((k >> 31) ? 0x80000000u : 0xFFFFFFFFu);
    return __uint_as_float(b);
}

// ============================================================
// Kernel A: causal QK^T -> score keys (128x128 tiles, 8x8/thread)
// (unchanged — measured ~90% of FFMA roofline)
// ============================================================
#define TILE 128
#define APAD 132
#define A_SMEM (2 * 64 * APAD * 4)   // 67584 bytes

__global__ void __launch_bounds__(256, 2)
qk_kernel(const float* __restrict__ Qg, const float* __restrict__ Kg)
{
    extern __shared__ float sm[];
    float* Qs = sm;
    float* Ks = sm + 64 * APAD;

    int t = (gridDim.x - 1) - blockIdx.x;
    int qt = (int)((sqrtf(8.f * (float)t + 1.f) - 1.f) * 0.5f);
    while ((qt + 1) * (qt + 2) / 2 <= t) qt++;
    while (qt * (qt + 1) / 2 > t) qt--;
    int kt = t - qt * (qt + 1) / 2;

    const int bh = blockIdx.y;
    const int qbase = qt * TILE, kbase = kt * TILE;
    const int tid = threadIdx.x;

    const float* Qp = Qg + ((size_t)bh * SL + qbase) * HD;
    const float* Kp = Kg + ((size_t)bh * SL + kbase) * HD;

    #pragma unroll
    for (int it = 0; it < 8; it++) {
        int idx = it * 256 + tid;
        int r = idx >> 4, c = idx & 15;
        float4 v = ((const float4*)(Qp + (size_t)r * HD))[c];
        Qs[(4 * c + 0) * APAD + r] = v.x; Qs[(4 * c + 1) * APAD + r] = v.y;
        Qs[(4 * c + 2) * APAD + r] = v.z; Qs[(4 * c + 3) * APAD + r] = v.w;
        float4 w = ((const float4*)(Kp + (size_t)r * HD))[c];
        Ks[(4 * c + 0) * APAD + r] = w.x; Ks[(4 * c + 1) * APAD + r] = w.y;
        Ks[(4 * c + 2) * APAD + r] = w.z; Ks[(4 * c + 3) * APAD + r] = w.w;
    }
    __syncthreads();

    const int tx = tid & 15, ty = tid >> 4;
    const int q0 = ty * 8, k0 = tx * 8;

    float acc[8][8] = {};
    #pragma unroll 4
    for (int d = 0; d < 64; d++) {
        float a[8], b[8];
        *(float4*)&a[0] = *(const float4*)&Qs[d * APAD + q0];
        *(float4*)&a[4] = *(const float4*)&Qs[d * APAD + q0 + 4];
        *(float4*)&b[0] = *(const float4*)&Ks[d * APAD + k0];
        *(float4*)&b[4] = *(const float4*)&Ks[d * APAD + k0 + 4];
        #pragma unroll
        for (int i = 0; i < 8; i++)
            #pragma unroll
            for (int j = 0; j < 8; j++)
                acc[i][j] = fmaf(a[i], b[j], acc[i][j]);
    }

    const bool diag = (qt == kt);
    #pragma unroll
    for (int i = 0; i < 8; i++) {
        const int qg = qbase + q0 + i;
        uint32_t* row = g_keys + ((size_t)bh * SL + qg) * SL + kbase + k0;
        uint4 lo, hi;
        if (diag) {
            int ql = q0 + i;
            lo.x = f2k((k0     <= ql) ? acc[i][0] : NEGMAX);
            lo.y = f2k((k0 + 1 <= ql) ? acc[i][1] : NEGMAX);
            lo.z = f2k((k0 + 2 <= ql) ? acc[i][2] : NEGMAX);
            lo.w = f2k((k0 + 3 <= ql) ? acc[i][3] : NEGMAX);
            hi.x = f2k((k0 + 4 <= ql) ? acc[i][4] : NEGMAX);
            hi.y = f2k((k0 + 5 <= ql) ? acc[i][5] : NEGMAX);
            hi.z = f2k((k0 + 6 <= ql) ? acc[i][6] : NEGMAX);
            hi.w = f2k((k0 + 7 <= ql) ? acc[i][7] : NEGMAX);
        } else {
            lo.x = f2k(acc[i][0]); lo.y = f2k(acc[i][1]);
            lo.z = f2k(acc[i][2]); lo.w = f2k(acc[i][3]);
            hi.x = f2k(acc[i][4]); hi.y = f2k(acc[i][5]);
            hi.z = f2k(acc[i][6]); hi.w = f2k(acc[i][7]);
        }
        *(uint4*)row = lo;
        *(uint4*)(row + 4) = hi;
    }
}

// ============================================================
// Kernel B: streaming top-128 select + softmax + PV gather
// ============================================================
#define CAP 768
#define PRUNE_HI (CAP - 128)   // 640: max growth per check is 128
// per-warp u32 layout: buf u64[768] (1536) | hist 256 | selp u64[128] (256) = 2048 u32 = 8KB
#define WSTRIDE 2048
#define B_SMEM (8 * WSTRIDE * 4)    // 65536 bytes -> 3 CTAs/SM

// descending bin scan: hist[256], rank r (1-based from top) -> bin B, r = rank within B
__device__ __forceinline__ void bin_scan(const uint32_t* hist, int lane, int& r, int& B) {
    const unsigned FULL = 0xFFFFFFFFu;
    int rev[8]; int s = 0;
    #pragma unroll
    for (int t = 0; t < 8; t++) { rev[t] = (int)hist[255 - (lane * 8 + t)]; s += rev[t]; }
    int inc = s;
    #pragma unroll
    for (int o = 1; o < 32; o <<= 1) {
        int v = __shfl_up_sync(FULL, inc, o);
        if (lane >= o) inc += v;
    }
    int pre = inc - s;
    int cum = pre, Bl = -1, rsub = 0;
    #pragma unroll
    for (int t = 0; t < 8; t++) {
        cum += rev[t];
        if (Bl < 0 && cum >= r) { Bl = 255 - (lane * 8 + t); rsub = r - (cum - rev[t]); }
    }
    unsigned bal = __ballot_sync(FULL, Bl >= 0);
    int src = __ffs(bal) - 1;
    B = __shfl_sync(FULL, Bl, src);
    r = __shfl_sync(FULL, rsub, src);
}

__global__ void __launch_bounds__(256, 3)
sel_kernel(const float* __restrict__ Vg, float* __restrict__ Og)
{
    extern __shared__ uint32_t smb[];
    const int tid = threadIdx.x;
    const int warp = tid >> 5, lane = tid & 31;
    const unsigned FULL = 0xFFFFFFFFu;
    const uint32_t lmask = (1u << lane) - 1u;
    const float scale = 0.125f;   // 64^-0.5

    uint32_t* wmem = smb + warp * WSTRIDE;
    u64* buf  = (u64*)wmem;                     // [CAP]
    uint32_t* hist = wmem + 2 * CAP;            // [256]
    u64* selp = (u64*)(wmem + 2 * CAP + 256);   // [128] packed (w_bits<<32 | idx)

    const int bh = blockIdx.y;
    const int qg = ((gridDim.x - 1) - blockIdx.x) * 8 + warp;   // heavy rows first
    const int n  = qg + 1;
    const uint32_t* krow = g_keys + ((size_t)bh * SL + qg) * SL;
    const uint4* kr4 = (const uint4*)krow;
    const int n4 = n >> 2;

    // ---- initial threshold guess (safe-by-verification; ~11 sigma margin) ----
    uint32_t T0key = 0;
    if (n >= 512) {
        float lg = log2f((float)n * (1.0f / 128.0f));      // 2..4
        float t0 = 8.0f * (1.534f * lg * 0.25f) - 4.0f;
        T0key = f2k(t0);
    }

    // ---- streaming pass (retry with T=0 if the guess filtered too much) ----
    int cnt = 0, total = 0;
    for (int attempt = 0; ; attempt++) {
        uint32_t Tcur = attempt ? 0u : T0key;
        cnt = 0; total = 0;

        for (int base = 0; base < n4; base += 32) {
            int i4 = base + lane;
            bool valid = i4 < n4;
            uint4 x = valid ? kr4[i4] : make_uint4(0, 0, 0, 0);
            #pragma unroll
            for (int c = 0; c < 4; c++) {
                uint32_t k = (c == 0) ? x.x : (c == 1) ? x.y : (c == 2) ? x.z : x.w;
                bool p = valid && (k >= Tcur);
                unsigned bal = __ballot_sync(FULL, p);
                if (p) {
                    int idx = 4 * i4 + c;
                    buf[cnt + __popc(bal & lmask)] = ((u64)k << 32) | (uint32_t)(SL - 1 - idx);
                }
                cnt   += __popc(bal);
                total += __popc(bal);
            }

            if (cnt > PRUNE_HI) {
                // EXACT prune: find the buffer's 128th-largest u64 (count-only
                // byte descent; u64s unique), keep exactly the top 128.
                u64 prefix = 0, pmask = 0;
                int rr = TOPKK;
                #pragma unroll 1
                for (int level = 7; level >= 0; level--) {
                    #pragma unroll
                    for (int t = 0; t < 8; t++) hist[lane + 32 * t] = 0;
                    __syncwarp();
                    for (int b2 = 0; b2 < cnt; b2 += 32) {
                        int i = b2 + lane;
                        bool valid2 = i < cnt;
                        u64 v = valid2 ? buf[i] : 0;
                        bool ok = valid2 && ((v & pmask) == prefix);
                        uint32_t bb = ok ? (uint32_t)((v >> (8 * level)) & 255) : 0x100u;
                        unsigned grp = __match_any_sync(FULL, bb);
                        if (ok && lane == __ffs(grp) - 1) atomicAdd(&hist[bb], __popc(grp));
                    }
                    __syncwarp();
                    int B; bin_scan(hist, lane, rr, B);
                    prefix |= ((u64)(uint32_t)B) << (8 * level);
                    pmask  |= ((u64)0xFF) << (8 * level);
                }
                const u64 T128 = prefix;
                int nc = 0;
                for (int b2 = 0; b2 < cnt; b2 += 32) {
                    int i = b2 + lane;
                    u64 v = (i < cnt) ? buf[i] : 0;
                    bool keep = (i < cnt) && (v >= T128);
                    unsigned bal = __ballot_sync(FULL, keep);
                    if (keep) buf[nc + __popc(bal & lmask)] = v;
                    nc += __popc(bal);
                }
                __syncwarp();
                cnt = nc;                       // exactly 128
                Tcur = (uint32_t)(T128 >> 32);  // admit equal keys (ties safe)
            }
        }
        // tail (n % 4 elements)
        {
            int rem = n & 3;
            int i = (n4 << 2) + lane;
            uint32_t k = (lane < rem) ? krow[i] : 0u;
            bool p = (lane < rem) && (k >= Tcur);
            unsigned bal = __ballot_sync(FULL, p);
            if (p) buf[cnt + __popc(bal & lmask)] = ((u64)k << 32) | (uint32_t)(SL - 1 - i);
            cnt   += __popc(bal);
            total += __popc(bal);
        }

        if (n <= TOPKK || total >= TOPKK) break;   // verified: top-128 fully captured
    }

    // ---- exact select on the buffer ----
    int selc = 0;
    float dsum = 0.f;

    if (n <= TOPKK) {
        for (int i = lane; i < cnt; i += 32) {     // no sync intrinsics inside
            u64 v = buf[i];
            float w = __expf(k2f((uint32_t)(v >> 32)) * scale);
            int idx = SL - 1 - (int)(uint32_t)(v & 0xFFFFFFFFu);
            selp[i] = ((u64)__float_as_uint(w) << 32) | (uint32_t)idx;
            dsum += w;
        }
        selc = cnt;
    } else {
        int r = TOPKK;
        int mm = cnt;
        float ref = 0.f;

        #pragma unroll 1
        for (int level = 7; level >= 0 && mm != r; level--) {
            // histogram of byte `level` over buf[0..mm)
            #pragma unroll
            for (int t = 0; t < 8; t++) hist[lane + 32 * t] = 0;
            __syncwarp();
            for (int base = 0; base < mm; base += 32) {
                int i = base + lane;
                bool valid = i < mm;
                uint32_t bb = valid ? (uint32_t)((buf[i] >> (8 * level)) & 255) : 0x100u;
                unsigned grp = __match_any_sync(FULL, bb);
                if (valid && lane == __ffs(grp) - 1) atomicAdd(&hist[bb], __popc(grp));
            }
            __syncwarp();
            int B; bin_scan(hist, lane, r, B);
            if (level == 7) ref = k2f(((uint32_t)B) << 24);

            // sure-append (byte > B), compact bucket (== B) to front
            int nb = 0;
            for (int base = 0; base < mm; base += 32) {
                int i = base + lane;
                u64 v = (i < mm) ? buf[i] : 0;
                int bb = (i < mm) ? (int)((v >> (8 * level)) & 255) : -1;
                bool sure = bb > B;
                bool inb  = bb == B;
                unsigned sbal = __ballot_sync(FULL, sure);
                unsigned bbal = __ballot_sync(FULL, inb);
                if (sure) {
                    float w = __expf((k2f((uint32_t)(v >> 32)) - ref) * scale);
                    int idx = SL - 1 - (int)(uint32_t)(v & 0xFFFFFFFFu);
                    selp[selc + __popc(sbal & lmask)] =
                        ((u64)__float_as_uint(w) << 32) | (uint32_t)idx;
                    dsum += w;
                }
                if (inb) buf[nb + __popc(bbal & lmask)] = v;
                selc += __popc(sbal);
                nb   += __popc(bbal);
            }
            mm = nb;
            __syncwarp();
        }

        // bucket now holds exactly r elements (u64s unique) — take them all
        for (int i = lane; i < mm; i += 32) {      // no sync intrinsics inside
            u64 v = buf[i];
            float w = __expf((k2f((uint32_t)(v >> 32)) - ref) * scale);
            int idx = SL - 1 - (int)(uint32_t)(v & 0xFFFFFFFFu);
            selp[selc + i] = ((u64)__float_as_uint(w) << 32) | (uint32_t)idx;
            dsum += w;
        }
        selc += mm;
    }

    #pragma unroll
    for (int o = 16; o > 0; o >>= 1) dsum += __shfl_xor_sync(FULL, dsum, o);
    const float inv = 1.f / dsum;
    __syncwarp();

    // ---- PV gather: float2 per lane, 8-deep MLP ----
    const float2* V2 = (const float2*)(Vg + (size_t)bh * SL * HD);
    const int S = selc;
    float ax = 0.f, ay = 0.f;
    int t = 0;
    for (; t + 8 <= S; t += 8) {
        u64 e[8]; float2 vv[8];
        #pragma unroll
        for (int u = 0; u < 8; u++) e[u] = selp[t + u];
        #pragma unroll
        for (int u = 0; u < 8; u++)
            vv[u] = V2[(size_t)(uint32_t)(e[u] & 0xFFFFFFFFu) * 32 + lane];
        #pragma unroll
        for (int u = 0; u < 8; u++) {
            float w = __uint_as_float((uint32_t)(e[u] >> 32));
            ax = fmaf(w, vv[u].x, ax);
            ay = fmaf(w, vv[u].y, ay);
        }
    }
    for (; t < S; t++) {
        u64 e = selp[t];
        float w = __uint_as_float((uint32_t)(e >> 32));
        float2 v = V2[(size_t)(uint32_t)(e & 0xFFFFFFFFu) * 32 + lane];
        ax = fmaf(w, v.x, ax); ay = fmaf(w, v.y, ay);
    }

    float2* orow = (float2*)(Og + ((size_t)bh * SL + qg) * HD);
    orow[lane] = make_float2(ax * inv, ay * inv);
}

// ============================================================
extern "C" void kernel_launch(void* const* d_in, const int* in_sizes, int n_in,
                              void* d_out, int out_size) {
    (void)in_sizes; (void)n_in; (void)out_size;
    const float* Q = (const float*)d_in[0];
    const float* K = (const float*)d_in[1];
    const float* V = (const float*)d_in[2];
    float* O = (float*)d_out;

    cudaFuncSetAttribute(qk_kernel,  cudaFuncAttributeMaxDynamicSharedMemorySize, A_SMEM);
    cudaFuncSetAttribute(sel_kernel, cudaFuncAttributeMaxDynamicSharedMemorySize, B_SMEM);

    const int ntiles = (SL / TILE) * (SL / TILE + 1) / 2;   // 136
    dim3 gridA(ntiles, NB * NH);
    qk_kernel<<<gridA, 256, A_SMEM>>>(Q, K);

    dim3 gridB(SL / 8, NB * NH);    // (256, 64)
    sel_kernel<<<gridB, 256, B_SMEM>>>(V, O);
}